// round 2
// baseline (speedup 1.0000x reference)
#include <cuda_runtime.h>
#include <cstdint>
#include <cstddef>

#define N_NODES 12288
#define F 128
#define BM 64
#define BK 32
#define STAGES (N_NODES / BK)   // 384

#define A_STRIDE 36             // pos/neg/edge tiles [BM][A_STRIDE]
#define B_STRIDE 136            // feats tile [BK][B_STRIDE]
#define STAGE_FLOATS (3 * BM * A_STRIDE + BK * B_STRIDE)   // 6912 + 4352 = 11264
#define SMEM_BYTES (2 * STAGE_FLOATS * 4)                  // 90112

// Scratch: S planes S1=pos@feats, S2=neg@feats, S3=edge@feats  (fp32, 18.9 MB)
__device__ float g_S[(size_t)3 * N_NODES * F];

__device__ __forceinline__ float rna_tf32(float x) {
    uint32_t r;
    asm("cvt.rna.tf32.f32 %0, %1;" : "=r"(r) : "f"(x));
    return __uint_as_float(r);
}

__device__ __forceinline__ void mma_tf32(float* d,
                                         uint32_t a0, uint32_t a1, uint32_t a2, uint32_t a3,
                                         uint32_t b0, uint32_t b1) {
    asm volatile(
        "mma.sync.aligned.m16n8k8.row.col.f32.tf32.tf32.f32 "
        "{%0,%1,%2,%3}, {%4,%5,%6,%7}, {%8,%9}, {%0,%1,%2,%3};\n"
        : "+f"(d[0]), "+f"(d[1]), "+f"(d[2]), "+f"(d[3])
        : "r"(a0), "r"(a1), "r"(a2), "r"(a3), "r"(b0), "r"(b1));
}

// ---------------------------------------------------------------------------
// Main kernel: S[p] = mask_p(adj) @ feats  for p in {pos(node), neg(node), edge}
// Tile: BM=64 rows x 128 cols (full feature width) x K=12288, tf32 tensor cores.
// ---------------------------------------------------------------------------
__global__ __launch_bounds__(512, 1)
void spmm3_kernel(const float* __restrict__ feats,
                  const float* __restrict__ node_adj,
                  const float* __restrict__ edge_adj) {
    extern __shared__ float sm[];

    const int tid = threadIdx.x;
    const int M0  = blockIdx.x * BM;

    const int wid  = tid >> 5;
    const int lane = tid & 31;
    const int gid  = lane >> 2;     // 0..7
    const int tig  = lane & 3;      // 0..3
    const int wm   = (wid & 3) * 16;    // warp row offset within tile (0..48)
    const int wn   = (wid >> 2) * 32;   // warp col offset (0..96)

    // global-load mapping (per stage)
    const int lrow = tid >> 3;          // 0..63
    const int lc4  = (tid & 7) * 4;     // 0..28
    const int fr0  = tid >> 5;          // 0..15
    const int fr1  = fr0 + 16;          // 16..31
    const int fc4  = (tid & 31) * 4;    // 0..124

    const float* nptr = node_adj + (size_t)(M0 + lrow) * N_NODES + lc4;
    const float* eptr = edge_adj + (size_t)(M0 + lrow) * N_NODES + lc4;

    float acc[3][4][4];
#pragma unroll
    for (int p = 0; p < 3; ++p)
#pragma unroll
        for (int j = 0; j < 4; ++j)
#pragma unroll
            for (int q = 0; q < 4; ++q) acc[p][j][q] = 0.f;

    float4 nv, ev, fv0, fv1;

    // ---- stage load helpers (inlined manually) ----
    // prologue: load + store stage 0
    nv  = *(const float4*)(nptr);
    ev  = *(const float4*)(eptr);
    fv0 = *(const float4*)(feats + (size_t)fr0 * F + fc4);
    fv1 = *(const float4*)(feats + (size_t)fr1 * F + fc4);

    {
        float* pb = sm;  // buffer 0
        float* posS = pb;
        float* negS = pb + BM * A_STRIDE;
        float* edgS = pb + 2 * BM * A_STRIDE;
        float* fS   = pb + 3 * BM * A_STRIDE;
        float4 p4, n4, e4, g0, g1;
        p4.x = nv.x > 0.f ? 1.f : 0.f;  n4.x = nv.x < 0.f ? 1.f : 0.f;
        p4.y = nv.y > 0.f ? 1.f : 0.f;  n4.y = nv.y < 0.f ? 1.f : 0.f;
        p4.z = nv.z > 0.f ? 1.f : 0.f;  n4.z = nv.z < 0.f ? 1.f : 0.f;
        p4.w = nv.w > 0.f ? 1.f : 0.f;  n4.w = nv.w < 0.f ? 1.f : 0.f;
        e4.x = rna_tf32(ev.x); e4.y = rna_tf32(ev.y); e4.z = rna_tf32(ev.z); e4.w = rna_tf32(ev.w);
        g0.x = rna_tf32(fv0.x); g0.y = rna_tf32(fv0.y); g0.z = rna_tf32(fv0.z); g0.w = rna_tf32(fv0.w);
        g1.x = rna_tf32(fv1.x); g1.y = rna_tf32(fv1.y); g1.z = rna_tf32(fv1.z); g1.w = rna_tf32(fv1.w);
        *(float4*)(posS + lrow * A_STRIDE + lc4) = p4;
        *(float4*)(negS + lrow * A_STRIDE + lc4) = n4;
        *(float4*)(edgS + lrow * A_STRIDE + lc4) = e4;
        *(float4*)(fS + fr0 * B_STRIDE + fc4) = g0;
        *(float4*)(fS + fr1 * B_STRIDE + fc4) = g1;
    }
    __syncthreads();

#pragma unroll 1
    for (int s = 0; s < STAGES; ++s) {
        // prefetch next stage into registers
        if (s + 1 < STAGES) {
            const int k0 = (s + 1) * BK;
            nv  = *(const float4*)(nptr + k0);
            ev  = *(const float4*)(eptr + k0);
            fv0 = *(const float4*)(feats + (size_t)(k0 + fr0) * F + fc4);
            fv1 = *(const float4*)(feats + (size_t)(k0 + fr1) * F + fc4);
        }

        // compute current stage
        {
            const float* pb   = sm + (size_t)(s & 1) * STAGE_FLOATS;
            const float* posS = pb;
            const float* negS = pb + BM * A_STRIDE;
            const float* edgS = pb + 2 * BM * A_STRIDE;
            const float* fS   = pb + 3 * BM * A_STRIDE;
#pragma unroll
            for (int kk = 0; kk < 4; ++kk) {
                const int kb = kk * 8;
                uint32_t bb[4][2];
#pragma unroll
                for (int j = 0; j < 4; ++j) {
                    const int nc = wn + j * 8 + gid;
                    bb[j][0] = __float_as_uint(fS[(kb + tig) * B_STRIDE + nc]);
                    bb[j][1] = __float_as_uint(fS[(kb + tig + 4) * B_STRIDE + nc]);
                }
#pragma unroll
                for (int p = 0; p < 3; ++p) {
                    const float* X = (p == 0) ? posS : (p == 1) ? negS : edgS;
                    const uint32_t a0 = __float_as_uint(X[(wm + gid) * A_STRIDE + kb + tig]);
                    const uint32_t a1 = __float_as_uint(X[(wm + gid + 8) * A_STRIDE + kb + tig]);
                    const uint32_t a2 = __float_as_uint(X[(wm + gid) * A_STRIDE + kb + tig + 4]);
                    const uint32_t a3 = __float_as_uint(X[(wm + gid + 8) * A_STRIDE + kb + tig + 4]);
#pragma unroll
                    for (int j = 0; j < 4; ++j)
                        mma_tf32(acc[p][j], a0, a1, a2, a3, bb[j][0], bb[j][1]);
                }
            }
        }

        // store next stage
        if (s + 1 < STAGES) {
            __syncthreads();
            float* pb   = sm + (size_t)((s + 1) & 1) * STAGE_FLOATS;
            float* posS = pb;
            float* negS = pb + BM * A_STRIDE;
            float* edgS = pb + 2 * BM * A_STRIDE;
            float* fS   = pb + 3 * BM * A_STRIDE;
            float4 p4, n4, e4, g0, g1;
            p4.x = nv.x > 0.f ? 1.f : 0.f;  n4.x = nv.x < 0.f ? 1.f : 0.f;
            p4.y = nv.y > 0.f ? 1.f : 0.f;  n4.y = nv.y < 0.f ? 1.f : 0.f;
            p4.z = nv.z > 0.f ? 1.f : 0.f;  n4.z = nv.z < 0.f ? 1.f : 0.f;
            p4.w = nv.w > 0.f ? 1.f : 0.f;  n4.w = nv.w < 0.f ? 1.f : 0.f;
            e4.x = rna_tf32(ev.x); e4.y = rna_tf32(ev.y); e4.z = rna_tf32(ev.z); e4.w = rna_tf32(ev.w);
            g0.x = rna_tf32(fv0.x); g0.y = rna_tf32(fv0.y); g0.z = rna_tf32(fv0.z); g0.w = rna_tf32(fv0.w);
            g1.x = rna_tf32(fv1.x); g1.y = rna_tf32(fv1.y); g1.z = rna_tf32(fv1.z); g1.w = rna_tf32(fv1.w);
            *(float4*)(posS + lrow * A_STRIDE + lc4) = p4;
            *(float4*)(negS + lrow * A_STRIDE + lc4) = n4;
            *(float4*)(edgS + lrow * A_STRIDE + lc4) = e4;
            *(float4*)(fS + fr0 * B_STRIDE + fc4) = g0;
            *(float4*)(fS + fr1 * B_STRIDE + fc4) = g1;
            __syncthreads();
        }
    }

    // epilogue: write S planes (fp32)
#pragma unroll
    for (int p = 0; p < 3; ++p) {
        float* base = g_S + ((size_t)p * N_NODES + M0 + wm + gid) * F;
#pragma unroll
        for (int j = 0; j < 4; ++j) {
            const int col = wn + j * 8 + tig * 2;
            *(float2*)(base + col)         = make_float2(acc[p][j][0], acc[p][j][1]);
            *(float2*)(base + 8 * F + col) = make_float2(acc[p][j][2], acc[p][j][3]);
        }
    }
}

// ---------------------------------------------------------------------------
// Combine: out = relu(S1@Wn[0:128] + S2@Wn[128:256] + nb) + S3@We + eb
// ---------------------------------------------------------------------------
__device__ __forceinline__ void accum_block(const float* __restrict__ W,
                                            const float* __restrict__ S,
                                            float* acc,
                                            float* Ws, float* Ss,
                                            int tid, int tx, int ty, int R0) {
#pragma unroll 1
    for (int k0 = 0; k0 < 128; k0 += 32) {
        __syncthreads();
#pragma unroll
        for (int i = 0; i < 4; ++i) {
            const int e = tid + i * 256;
            const int wrow = e >> 5;
            const int wc = (e & 31) * 4;
            *(float4*)(Ws + wrow * 128 + wc) = *(const float4*)(W + (k0 + wrow) * 128 + wc);
        }
#pragma unroll
        for (int i = 0; i < 2; ++i) {
            const int e = tid + i * 256;
            const int srow = e >> 3;
            const int sc = (e & 7) * 4;
            *(float4*)(Ss + srow * 36 + sc) =
                *(const float4*)(S + (size_t)(R0 + srow) * F + k0 + sc);
        }
        __syncthreads();
#pragma unroll 8
        for (int kk = 0; kk < 32; ++kk) {
            float w[4], sv[8];
#pragma unroll
            for (int v = 0; v < 4; ++v) w[v] = Ws[kk * 128 + tx + 32 * v];
#pragma unroll
            for (int u = 0; u < 8; ++u) sv[u] = Ss[(ty + 8 * u) * 36 + kk];
#pragma unroll
            for (int u = 0; u < 8; ++u)
#pragma unroll
                for (int v = 0; v < 4; ++v)
                    acc[u * 4 + v] = fmaf(sv[u], w[v], acc[u * 4 + v]);
        }
    }
}

__global__ __launch_bounds__(256, 1)
void combine_kernel(const float* __restrict__ node_weight,
                    const float* __restrict__ node_bias,
                    const float* __restrict__ edge_weight,
                    const float* __restrict__ edge_bias,
                    float* __restrict__ out) {
    __shared__ float Ws[32 * 128];
    __shared__ float Ss[64 * 36];

    const int tid = threadIdx.x;
    const int tx = tid & 31;
    const int ty = tid >> 5;
    const int R0 = blockIdx.x * 64;

    float accN[32], accE[32];
#pragma unroll
    for (int i = 0; i < 32; ++i) { accN[i] = 0.f; accE[i] = 0.f; }

    accum_block(node_weight,             g_S,                               accN, Ws, Ss, tid, tx, ty, R0);
    accum_block(node_weight + 128 * 128, g_S + (size_t)N_NODES * F,        accN, Ws, Ss, tid, tx, ty, R0);
    accum_block(edge_weight,             g_S + (size_t)2 * N_NODES * F,    accE, Ws, Ss, tid, tx, ty, R0);

    float nb[4], eb[4];
#pragma unroll
    for (int v = 0; v < 4; ++v) {
        nb[v] = node_bias[tx + 32 * v];
        eb[v] = edge_bias[tx + 32 * v];
    }
#pragma unroll
    for (int u = 0; u < 8; ++u)
#pragma unroll
        for (int v = 0; v < 4; ++v) {
            const int r = R0 + ty + 8 * u;
            const int c = tx + 32 * v;
            out[(size_t)r * F + c] =
                fmaxf(accN[u * 4 + v] + nb[v], 0.f) + accE[u * 4 + v] + eb[v];
        }
}

extern "C" void kernel_launch(void* const* d_in, const int* in_sizes, int n_in,
                              void* d_out, int out_size) {
    const float* feats       = (const float*)d_in[0];
    const float* node_adj    = (const float*)d_in[1];
    const float* edge_adj    = (const float*)d_in[2];
    const float* node_weight = (const float*)d_in[3];
    const float* node_bias   = (const float*)d_in[4];
    const float* edge_weight = (const float*)d_in[5];
    const float* edge_bias   = (const float*)d_in[6];
    float* out = (float*)d_out;

    cudaFuncSetAttribute(spmm3_kernel, cudaFuncAttributeMaxDynamicSharedMemorySize, SMEM_BYTES);

    spmm3_kernel<<<N_NODES / BM, 512, SMEM_BYTES>>>(feats, node_adj, edge_adj);
    combine_kernel<<<N_NODES / 64, 256>>>(node_weight, node_bias, edge_weight, edge_bias, out);
}

// round 5
// speedup vs baseline: 1.8713x; 1.8713x over previous
#include <cuda_runtime.h>
#include <cuda_fp16.h>
#include <cstdint>
#include <cstddef>

#define N_NODES 12288
#define F 128
#define BM 48
#define BK 64
#define STAGES (N_NODES / BK)      // 192
#define THREADS 192
#define GRID (N_NODES / BM)        // 256

#define A_BYTES (BM * 128)         // 6144 per A matrix (48 rows x 128B)
#define ST_A3   (3 * A_BYTES)      // 18432: [pos][neg][edge]
#define B_BYTES (128 * 128)        // 16384: featsT tile 128n x 64k fp16
#define STAGE_BYTES (ST_A3 + B_BYTES)   // 34816
#define SMEM_TOTAL  (2 * STAGE_BYTES)   // 69632

// Scratch: S planes (fp32) + pre-swizzled fp16 featsT tiles per K-stage
__device__ float g_S[(size_t)3 * N_NODES * F];
__device__ uint4 g_fB[(size_t)STAGES * B_BYTES / 16];

// ---------------------------------------------------------------------------
// helpers
// ---------------------------------------------------------------------------
__device__ __forceinline__ uint32_t smem_u32(const void* p) {
    uint32_t a;
    asm("{ .reg .u64 t; cvta.to.shared.u64 t, %1; cvt.u32.u64 %0, t; }"
        : "=r"(a) : "l"(p));
    return a;
}

__device__ __forceinline__ uint32_t pack_h2(float lo, float hi) {
    __half2 h = __floats2half2_rn(lo, hi);
    return *(uint32_t*)&h;
}

#define SWX(off) ((off) ^ (((off) >> 3) & 0x70))

#define CP_ASYNC16(dst_u32, src) \
    asm volatile("cp.async.cg.shared.global [%0], [%1], 16;" \
                 :: "r"(dst_u32), "l"(src) : "memory")
#define CP_COMMIT() asm volatile("cp.async.commit_group;" ::: "memory")
#define CP_WAIT0()  asm volatile("cp.async.wait_group 0;" ::: "memory")

#define LDSM_X4(r0, r1, r2, r3, addr) \
    asm volatile("ldmatrix.sync.aligned.m8n8.x4.shared.b16 {%0,%1,%2,%3}, [%4];" \
                 : "=r"(r0), "=r"(r1), "=r"(r2), "=r"(r3) : "r"(addr))

__device__ __forceinline__ void mma_f16(float* d, const uint32_t* a,
                                        uint32_t b0, uint32_t b1) {
    asm volatile(
        "mma.sync.aligned.m16n8k16.row.col.f32.f16.f16.f32 "
        "{%0,%1,%2,%3}, {%4,%5,%6,%7}, {%8,%9}, {%0,%1,%2,%3};\n"
        : "+f"(d[0]), "+f"(d[1]), "+f"(d[2]), "+f"(d[3])
        : "r"(a[0]), "r"(a[1]), "r"(a[2]), "r"(a[3]), "r"(b0), "r"(b1));
}

// ---------------------------------------------------------------------------
// Prepass: pre-swizzled fp16 featsT tiles.
// Stage s, element (n, k') = feats[s*64 + k'][n] at byte SWX(n*128 + k'*2).
// ---------------------------------------------------------------------------
__global__ __launch_bounds__(256)
void prep_feats(const float* __restrict__ feats) {
    const int s = blockIdx.x;
    const int t = threadIdx.x;
    const int n = t >> 1;          // 0..127
    const int kh = (t & 1) * 32;   // k half
    uint32_t* out = (uint32_t*)g_fB + (size_t)s * (B_BYTES / 4);
    const float* src = feats + (size_t)(s * BK + kh) * F + n;
#pragma unroll
    for (int j = 0; j < 32; j += 2) {
        const float v0 = src[(size_t)j * F];
        const float v1 = src[(size_t)(j + 1) * F];
        const uint32_t off = (uint32_t)(n * 128 + (kh + j) * 2);
        out[SWX(off) >> 2] = pack_h2(v0, v1);
    }
}

// ---------------------------------------------------------------------------
// Main kernel: S[p] = mask_p @ feats via fp16 mma.sync m16n8k16.
// BM=48 rows/CTA, 6 warps (3m x 2n), double-buffered smem, occupancy 2.
// ---------------------------------------------------------------------------
__global__ __launch_bounds__(THREADS, 2)
void spmm3_f16(const float* __restrict__ node_adj,
               const float* __restrict__ edge_adj) {
    extern __shared__ char smem[];
    const uint32_t sb = smem_u32(smem);
    const int tid  = threadIdx.x;
    const int wid  = tid >> 5;
    const int lane = tid & 31;
    const int M0   = blockIdx.x * BM;

    // ---- converter mapping ----
    const int cm = tid >> 2;       // 0..47 row
    const int kq = tid & 3;        // 16-k group
    const float* nrow = node_adj + (size_t)(M0 + cm) * N_NODES + kq * 16;
    const float* erow = edge_adj + (size_t)(M0 + cm) * N_NODES + kq * 16;
    const uint32_t csts0 = SWX((uint32_t)(cm * 128 + kq * 32));
    const uint32_t csts1 = SWX((uint32_t)(cm * 128 + kq * 32 + 16));

    // ---- mma mapping ----
    const int wm = (wid % 3) * 16;
    const int wn = (wid / 3) * 64;
    // A ldmatrix address pieces
    const uint32_t arow = wm + (lane & 15);
    const uint32_t abase = arow * 128 + (lane >> 4) * 16;
    const uint32_t axor = (arow & 7) << 4;
    // B ldmatrix address pieces (4 n-pairs)
    uint32_t bbase[4], bxor[4];
#pragma unroll
    for (int np = 0; np < 4; ++np) {
        const uint32_t brow = wn + np * 16 + ((lane >> 4) << 3) + (lane & 7);
        bbase[np] = brow * 128 + ((lane >> 3) & 1) * 16;
        bxor[np]  = (brow & 7) << 4;
    }

    float acc[3][8][4];
#pragma unroll
    for (int p = 0; p < 3; ++p)
#pragma unroll
        for (int nt = 0; nt < 8; ++nt)
#pragma unroll
            for (int c = 0; c < 4; ++c) acc[p][nt][c] = 0.f;

    const char* fB = (const char*)g_fB;

    // ---- prologue: fill buffer 0 (stage 0) ----
    if (tid < 128) {
        const uint32_t dst = sb + ST_A3 + tid * 128;
        const char* src = fB + tid * 128;
#pragma unroll
        for (int q = 0; q < 8; ++q) CP_ASYNC16(dst + q * 16, src + q * 16);
    }
    CP_COMMIT();
    {
        float4 n0 = *(const float4*)(nrow);
        float4 n1 = *(const float4*)(nrow + 4);
        float4 n2 = *(const float4*)(nrow + 8);
        float4 n3 = *(const float4*)(nrow + 12);
        float4 e0 = *(const float4*)(erow);
        float4 e1 = *(const float4*)(erow + 4);
        float4 e2 = *(const float4*)(erow + 8);
        float4 e3 = *(const float4*)(erow + 12);
        uint4 P0, P1, Q0, Q1, E0, E1;
        P0 = make_uint4(pack_h2(n0.x > 0.f, n0.y > 0.f), pack_h2(n0.z > 0.f, n0.w > 0.f),
                        pack_h2(n1.x > 0.f, n1.y > 0.f), pack_h2(n1.z > 0.f, n1.w > 0.f));
        P1 = make_uint4(pack_h2(n2.x > 0.f, n2.y > 0.f), pack_h2(n2.z > 0.f, n2.w > 0.f),
                        pack_h2(n3.x > 0.f, n3.y > 0.f), pack_h2(n3.z > 0.f, n3.w > 0.f));
        Q0 = make_uint4(pack_h2(n0.x < 0.f, n0.y < 0.f), pack_h2(n0.z < 0.f, n0.w < 0.f),
                        pack_h2(n1.x < 0.f, n1.y < 0.f), pack_h2(n1.z < 0.f, n1.w < 0.f));
        Q1 = make_uint4(pack_h2(n2.x < 0.f, n2.y < 0.f), pack_h2(n2.z < 0.f, n2.w < 0.f),
                        pack_h2(n3.x < 0.f, n3.y < 0.f), pack_h2(n3.z < 0.f, n3.w < 0.f));
        E0 = make_uint4(pack_h2(e0.x, e0.y), pack_h2(e0.z, e0.w),
                        pack_h2(e1.x, e1.y), pack_h2(e1.z, e1.w));
        E1 = make_uint4(pack_h2(e2.x, e2.y), pack_h2(e2.z, e2.w),
                        pack_h2(e3.x, e3.y), pack_h2(e3.z, e3.w));
        *(uint4*)(smem + 0 * A_BYTES + csts0) = P0;
        *(uint4*)(smem + 0 * A_BYTES + csts1) = P1;
        *(uint4*)(smem + 1 * A_BYTES + csts0) = Q0;
        *(uint4*)(smem + 1 * A_BYTES + csts1) = Q1;
        *(uint4*)(smem + 2 * A_BYTES + csts0) = E0;
        *(uint4*)(smem + 2 * A_BYTES + csts1) = E1;
    }
    CP_WAIT0();
    __syncthreads();

    float4 nv[4], ev[4];

#pragma unroll 1
    for (int s = 0; s < STAGES; ++s) {
        const uint32_t cur = (uint32_t)(s & 1) * STAGE_BYTES;
        const uint32_t nxt = (uint32_t)((s + 1) & 1) * STAGE_BYTES;

        // (a) prefetch stage s+1: B via cp.async, adjacency via LDG regs
        if (s + 1 < STAGES) {
            if (tid < 128) {
                const uint32_t dst = sb + nxt + ST_A3 + tid * 128;
                const char* src = fB + (size_t)(s + 1) * B_BYTES + tid * 128;
#pragma unroll
                for (int q = 0; q < 8; ++q) CP_ASYNC16(dst + q * 16, src + q * 16);
            }
            CP_COMMIT();
            const size_t k0 = (size_t)(s + 1) * BK;
#pragma unroll
            for (int i = 0; i < 4; ++i) {
                nv[i] = *(const float4*)(nrow + k0 + i * 4);
                ev[i] = *(const float4*)(erow + k0 + i * 4);
            }
        }

        // (b) compute stage s
        const uint32_t sbA = sb + cur;
        const uint32_t sbB = sb + cur + ST_A3;
#pragma unroll
        for (int ks = 0; ks < 4; ++ks) {
            uint32_t b[4][4];
#pragma unroll
            for (int np = 0; np < 4; ++np)
                LDSM_X4(b[np][0], b[np][1], b[np][2], b[np][3],
                        sbB + ((bbase[np] + ks * 32) ^ bxor[np]));
#pragma unroll
            for (int p = 0; p < 3; ++p) {
                uint32_t a[4];
                LDSM_X4(a[0], a[1], a[2], a[3],
                        sbA + p * A_BYTES + ((abase + ks * 32) ^ axor));
#pragma unroll
                for (int np = 0; np < 4; ++np) {
                    mma_f16(acc[p][np * 2],     a, b[np][0], b[np][1]);
                    mma_f16(acc[p][np * 2 + 1], a, b[np][2], b[np][3]);
                }
            }
        }

        // (c) convert + store stage s+1 A tiles; drain B copy; barrier
        if (s + 1 < STAGES) {
            char* bp = smem + ((s + 1) & 1) * STAGE_BYTES;
            uint4 P0, P1, Q0, Q1, E0, E1;
            P0 = make_uint4(pack_h2(nv[0].x > 0.f, nv[0].y > 0.f), pack_h2(nv[0].z > 0.f, nv[0].w > 0.f),
                            pack_h2(nv[1].x > 0.f, nv[1].y > 0.f), pack_h2(nv[1].z > 0.f, nv[1].w > 0.f));
            P1 = make_uint4(pack_h2(nv[2].x > 0.f, nv[2].y > 0.f), pack_h2(nv[2].z > 0.f, nv[2].w > 0.f),
                            pack_h2(nv[3].x > 0.f, nv[3].y > 0.f), pack_h2(nv[3].z > 0.f, nv[3].w > 0.f));
            Q0 = make_uint4(pack_h2(nv[0].x < 0.f, nv[0].y < 0.f), pack_h2(nv[0].z < 0.f, nv[0].w < 0.f),
                            pack_h2(nv[1].x < 0.f, nv[1].y < 0.f), pack_h2(nv[1].z < 0.f, nv[1].w < 0.f));
            Q1 = make_uint4(pack_h2(nv[2].x < 0.f, nv[2].y < 0.f), pack_h2(nv[2].z < 0.f, nv[2].w < 0.f),
                            pack_h2(nv[3].x < 0.f, nv[3].y < 0.f), pack_h2(nv[3].z < 0.f, nv[3].w < 0.f));
            E0 = make_uint4(pack_h2(ev[0].x, ev[0].y), pack_h2(ev[0].z, ev[0].w),
                            pack_h2(ev[1].x, ev[1].y), pack_h2(ev[1].z, ev[1].w));
            E1 = make_uint4(pack_h2(ev[2].x, ev[2].y), pack_h2(ev[2].z, ev[2].w),
                            pack_h2(ev[3].x, ev[3].y), pack_h2(ev[3].z, ev[3].w));
            *(uint4*)(bp + 0 * A_BYTES + csts0) = P0;
            *(uint4*)(bp + 0 * A_BYTES + csts1) = P1;
            *(uint4*)(bp + 1 * A_BYTES + csts0) = Q0;
            *(uint4*)(bp + 1 * A_BYTES + csts1) = Q1;
            *(uint4*)(bp + 2 * A_BYTES + csts0) = E0;
            *(uint4*)(bp + 2 * A_BYTES + csts1) = E1;
            CP_WAIT0();
            __syncthreads();
        }
    }

    // ---- epilogue: acc -> g_S (fp32) ----
    const int er0 = wm + (lane >> 2);
    const int ec0 = wn + (lane & 3) * 2;
#pragma unroll
    for (int p = 0; p < 3; ++p) {
        float* base = g_S + ((size_t)p * N_NODES + M0 + er0) * F + ec0;
#pragma unroll
        for (int nt = 0; nt < 8; ++nt) {
            *(float2*)(base + nt * 8)           = make_float2(acc[p][nt][0], acc[p][nt][1]);
            *(float2*)(base + 8 * F + nt * 8)   = make_float2(acc[p][nt][2], acc[p][nt][3]);
        }
    }
}

// ---------------------------------------------------------------------------
// Combine: out = relu(S1@Wn[0:128] + S2@Wn[128:256] + nb) + S3@We + eb
// 32 rows per block, grid 384 (higher occupancy than R2's 64-row version)
// ---------------------------------------------------------------------------
__device__ __forceinline__ void accum_block(const float* __restrict__ W,
                                            const float* __restrict__ S,
                                            float* acc,
                                            float* Ws, float* Ss,
                                            int tid, int tx, int ty, int R0) {
#pragma unroll 1
    for (int k0 = 0; k0 < 128; k0 += 32) {
        __syncthreads();
#pragma unroll
        for (int i = 0; i < 4; ++i) {
            const int e = tid + i * 256;
            const int wrow = e >> 5;
            const int wc = (e & 31) * 4;
            *(float4*)(Ws + wrow * 128 + wc) = *(const float4*)(W + (k0 + wrow) * 128 + wc);
        }
        {
            const int srow = tid >> 3;
            const int sc = (tid & 7) * 4;
            *(float4*)(Ss + srow * 36 + sc) =
                *(const float4*)(S + (size_t)(R0 + srow) * F + k0 + sc);
        }
        __syncthreads();
#pragma unroll 8
        for (int kk = 0; kk < 32; ++kk) {
            float w[4], sv[4];
#pragma unroll
            for (int v = 0; v < 4; ++v) w[v] = Ws[kk * 128 + tx + 32 * v];
#pragma unroll
            for (int u = 0; u < 4; ++u) sv[u] = Ss[(ty + 8 * u) * 36 + kk];
#pragma unroll
            for (int u = 0; u < 4; ++u)
#pragma unroll
                for (int v = 0; v < 4; ++v)
                    acc[u * 4 + v] = fmaf(sv[u], w[v], acc[u * 4 + v]);
        }
    }
}

__global__ __launch_bounds__(256)
void combine_kernel(const float* __restrict__ node_weight,
                    const float* __restrict__ node_bias,
                    const float* __restrict__ edge_weight,
                    const float* __restrict__ edge_bias,
                    float* __restrict__ out) {
    __shared__ float Ws[32 * 128];
    __shared__ float Ss[32 * 36];

    const int tid = threadIdx.x;
    const int tx = tid & 31;
    const int ty = tid >> 5;
    const int R0 = blockIdx.x * 32;

    float accN[16], accE[16];
#pragma unroll
    for (int i = 0; i < 16; ++i) { accN[i] = 0.f; accE[i] = 0.f; }

    accum_block(node_weight,             g_S,                            accN, Ws, Ss, tid, tx, ty, R0);
    accum_block(node_weight + 128 * 128, g_S + (size_t)N_NODES * F,      accN, Ws, Ss, tid, tx, ty, R0);
    accum_block(edge_weight,             g_S + (size_t)2 * N_NODES * F,  accE, Ws, Ss, tid, tx, ty, R0);

    float nb[4], eb[4];
#pragma unroll
    for (int v = 0; v < 4; ++v) {
        nb[v] = node_bias[tx + 32 * v];
        eb[v] = edge_bias[tx + 32 * v];
    }
#pragma unroll
    for (int u = 0; u < 4; ++u)
#pragma unroll
        for (int v = 0; v < 4; ++v) {
            const int r = R0 + ty + 8 * u;
            const int c = tx + 32 * v;
            out[(size_t)r * F + c] =
                fmaxf(accN[u * 4 + v] + nb[v], 0.f) + accE[u * 4 + v] + eb[v];
        }
}

extern "C" void kernel_launch(void* const* d_in, const int* in_sizes, int n_in,
                              void* d_out, int out_size) {
    const float* feats       = (const float*)d_in[0];
    const float* node_adj    = (const float*)d_in[1];
    const float* edge_adj    = (const float*)d_in[2];
    const float* node_weight = (const float*)d_in[3];
    const float* node_bias   = (const float*)d_in[4];
    const float* edge_weight = (const float*)d_in[5];
    const float* edge_bias   = (const float*)d_in[6];
    float* out = (float*)d_out;

    cudaFuncSetAttribute(spmm3_f16, cudaFuncAttributeMaxDynamicSharedMemorySize, SMEM_TOTAL);

    prep_feats<<<STAGES, 256>>>(feats);
    spmm3_f16<<<GRID, THREADS, SMEM_TOTAL>>>(node_adj, edge_adj);
    combine_kernel<<<N_NODES / 32, 256>>>(node_weight, node_bias, edge_weight, edge_bias, out);
}

// round 6
// speedup vs baseline: 2.4190x; 1.2927x over previous
#include <cuda_runtime.h>
#include <cuda_fp16.h>
#include <cstdint>
#include <cstddef>

#define N_NODES 12288
#define F 128
#define BM 48
#define BK 64
#define STAGES (N_NODES / BK)      // 192
#define THREADS 192
#define GRID (N_NODES / BM)        // 256

#define A_BYTES (BM * 128)         // 6144 per A plane (48 rows x 128B)
#define ST_A2   (2 * A_BYTES)      // 12288: [sign][edge]
#define B_BYTES (128 * 128)        // 16384: featsT tile 128n x 64k fp16
#define STAGE_BYTES (ST_A2 + B_BYTES)   // 28672
#define SMEM_TOTAL  (2 * STAGE_BYTES)   // 57344

// Scratch
__device__ float g_S[(size_t)2 * N_NODES * F];       // [sign@f][edge@f]
__device__ uint4 g_fB[(size_t)STAGES * B_BYTES / 16]; // pre-swizzled fp16 featsT
__device__ float g_c[F];                              // colsum(feats)
__device__ float g_Wd[F * F];                         // (Wtop - Wbot)/2
__device__ float g_b2[F];                             // c@(Wtop+Wbot)/2 + nb

// ---------------------------------------------------------------------------
// helpers
// ---------------------------------------------------------------------------
__device__ __forceinline__ uint32_t smem_u32(const void* p) {
    uint32_t a;
    asm("{ .reg .u64 t; cvta.to.shared.u64 t, %1; cvt.u32.u64 %0, t; }"
        : "=r"(a) : "l"(p));
    return a;
}

__device__ __forceinline__ uint32_t pack_h2(float lo, float hi) {
    __half2 h = __floats2half2_rn(lo, hi);
    return *(uint32_t*)&h;
}

__device__ __forceinline__ float sgnf(float v) {
    return (v > 0.f ? 1.f : 0.f) - (v < 0.f ? 1.f : 0.f);
}

#define SWX(off) ((off) ^ (((off) >> 3) & 0x70))

#define CP_ASYNC16(dst_u32, src) \
    asm volatile("cp.async.cg.shared.global [%0], [%1], 16;" \
                 :: "r"(dst_u32), "l"(src) : "memory")
#define CP_COMMIT() asm volatile("cp.async.commit_group;" ::: "memory")
#define CP_WAIT0()  asm volatile("cp.async.wait_group 0;" ::: "memory")

#define LDSM_X4(r0, r1, r2, r3, addr) \
    asm volatile("ldmatrix.sync.aligned.m8n8.x4.shared.b16 {%0,%1,%2,%3}, [%4];" \
                 : "=r"(r0), "=r"(r1), "=r"(r2), "=r"(r3) : "r"(addr))

__device__ __forceinline__ void mma_f16(float* d, const uint32_t* a,
                                        uint32_t b0, uint32_t b1) {
    asm volatile(
        "mma.sync.aligned.m16n8k16.row.col.f32.f16.f16.f32 "
        "{%0,%1,%2,%3}, {%4,%5,%6,%7}, {%8,%9}, {%0,%1,%2,%3};\n"
        : "+f"(d[0]), "+f"(d[1]), "+f"(d[2]), "+f"(d[3])
        : "r"(a[0]), "r"(a[1]), "r"(a[2]), "r"(a[3]), "r"(b0), "r"(b1));
}

// ---------------------------------------------------------------------------
// Tiny prepass kernels
// ---------------------------------------------------------------------------
__global__ void zero_c_kernel() { g_c[threadIdx.x] = 0.f; }

__global__ __launch_bounds__(128)
void colsum_kernel(const float* __restrict__ feats) {
    const int t = threadIdx.x;
    const int r0 = blockIdx.x * 128;
    float s = 0.f;
#pragma unroll 4
    for (int r = 0; r < 128; ++r)
        s += feats[(size_t)(r0 + r) * F + t];
    atomicAdd(&g_c[t], s);
}

// Wd = (Wtop - Wbot)/2 ; b2 = nb + c @ (Wtop + Wbot)/2
__global__ __launch_bounds__(128)
void wtrans_kernel(const float* __restrict__ node_weight,
                   const float* __restrict__ node_bias) {
    const int j = threadIdx.x;
    float b = node_bias[j];
#pragma unroll 4
    for (int k = 0; k < 128; ++k) {
        const float wt = node_weight[(size_t)k * F + j];
        const float wb = node_weight[(size_t)(k + 128) * F + j];
        g_Wd[k * F + j] = 0.5f * (wt - wb);
        b += g_c[k] * 0.5f * (wt + wb);
    }
    g_b2[j] = b;
}

// ---------------------------------------------------------------------------
// Prepass: pre-swizzled fp16 featsT tiles.
// Stage s, element (n, k') = feats[s*64 + k'][n] at byte SWX(n*128 + k'*2).
// ---------------------------------------------------------------------------
__global__ __launch_bounds__(256)
void prep_feats(const float* __restrict__ feats) {
    const int s = blockIdx.x;
    const int t = threadIdx.x;
    const int n = t >> 1;          // 0..127
    const int kh = (t & 1) * 32;   // k half
    uint32_t* out = (uint32_t*)g_fB + (size_t)s * (B_BYTES / 4);
    const float* src = feats + (size_t)(s * BK + kh) * F + n;
#pragma unroll
    for (int j = 0; j < 32; j += 2) {
        const float v0 = src[(size_t)j * F];
        const float v1 = src[(size_t)(j + 1) * F];
        const uint32_t off = (uint32_t)(n * 128 + (kh + j) * 2);
        out[SWX(off) >> 2] = pack_h2(v0, v1);
    }
}

// ---------------------------------------------------------------------------
// Main kernel: S_sign = sign(node_adj) @ feats, S_edge = edge_adj @ feats
// via fp16 mma.sync m16n8k16. BM=48, 6 warps (3m x 2n), double-buffer, occ 2.
// ---------------------------------------------------------------------------
__global__ __launch_bounds__(THREADS, 2)
void spmm2_f16(const float* __restrict__ node_adj,
               const float* __restrict__ edge_adj) {
    extern __shared__ char smem[];
    const uint32_t sb = smem_u32(smem);
    const int tid  = threadIdx.x;
    const int wid  = tid >> 5;
    const int lane = tid & 31;
    const int M0   = blockIdx.x * BM;

    // ---- converter mapping ----
    const int cm = tid >> 2;       // 0..47 row
    const int kq = tid & 3;        // 16-k group
    const float* nrow = node_adj + (size_t)(M0 + cm) * N_NODES + kq * 16;
    const float* erow = edge_adj + (size_t)(M0 + cm) * N_NODES + kq * 16;
    const uint32_t csts0 = SWX((uint32_t)(cm * 128 + kq * 32));
    const uint32_t csts1 = SWX((uint32_t)(cm * 128 + kq * 32 + 16));

    // ---- mma mapping ----
    const int wm = (wid % 3) * 16;
    const int wn = (wid / 3) * 64;
    const uint32_t arow = wm + (lane & 15);
    const uint32_t abase = arow * 128 + (lane >> 4) * 16;
    const uint32_t axor = (arow & 7) << 4;
    uint32_t bbase[4], bxor[4];
#pragma unroll
    for (int np = 0; np < 4; ++np) {
        const uint32_t brow = wn + np * 16 + ((lane >> 4) << 3) + (lane & 7);
        bbase[np] = brow * 128 + ((lane >> 3) & 1) * 16;
        bxor[np]  = (brow & 7) << 4;
    }

    float acc[2][8][4];
#pragma unroll
    for (int p = 0; p < 2; ++p)
#pragma unroll
        for (int nt = 0; nt < 8; ++nt)
#pragma unroll
            for (int c = 0; c < 4; ++c) acc[p][nt][c] = 0.f;

    const char* fB = (const char*)g_fB;

    // ---- prologue: fill buffer 0 (stage 0) ----
    if (tid < 128) {
        const uint32_t dst = sb + ST_A2 + tid * 128;
        const char* src = fB + tid * 128;
#pragma unroll
        for (int q = 0; q < 8; ++q) CP_ASYNC16(dst + q * 16, src + q * 16);
    }
    CP_COMMIT();
    {
        float4 n0 = *(const float4*)(nrow);
        float4 n1 = *(const float4*)(nrow + 4);
        float4 n2 = *(const float4*)(nrow + 8);
        float4 n3 = *(const float4*)(nrow + 12);
        float4 e0 = *(const float4*)(erow);
        float4 e1 = *(const float4*)(erow + 4);
        float4 e2 = *(const float4*)(erow + 8);
        float4 e3 = *(const float4*)(erow + 12);
        uint4 S0, S1, E0, E1;
        S0 = make_uint4(pack_h2(sgnf(n0.x), sgnf(n0.y)), pack_h2(sgnf(n0.z), sgnf(n0.w)),
                        pack_h2(sgnf(n1.x), sgnf(n1.y)), pack_h2(sgnf(n1.z), sgnf(n1.w)));
        S1 = make_uint4(pack_h2(sgnf(n2.x), sgnf(n2.y)), pack_h2(sgnf(n2.z), sgnf(n2.w)),
                        pack_h2(sgnf(n3.x), sgnf(n3.y)), pack_h2(sgnf(n3.z), sgnf(n3.w)));
        E0 = make_uint4(pack_h2(e0.x, e0.y), pack_h2(e0.z, e0.w),
                        pack_h2(e1.x, e1.y), pack_h2(e1.z, e1.w));
        E1 = make_uint4(pack_h2(e2.x, e2.y), pack_h2(e2.z, e2.w),
                        pack_h2(e3.x, e3.y), pack_h2(e3.z, e3.w));
        *(uint4*)(smem + 0 * A_BYTES + csts0) = S0;
        *(uint4*)(smem + 0 * A_BYTES + csts1) = S1;
        *(uint4*)(smem + 1 * A_BYTES + csts0) = E0;
        *(uint4*)(smem + 1 * A_BYTES + csts1) = E1;
    }
    CP_WAIT0();
    __syncthreads();

    float4 nv[4], ev[4];

#pragma unroll 1
    for (int s = 0; s < STAGES; ++s) {
        const uint32_t cur = (uint32_t)(s & 1) * STAGE_BYTES;
        const uint32_t nxt = (uint32_t)((s + 1) & 1) * STAGE_BYTES;

        // (a) prefetch stage s+1: B via cp.async, adjacency via LDG regs
        if (s + 1 < STAGES) {
            if (tid < 128) {
                const uint32_t dst = sb + nxt + ST_A2 + tid * 128;
                const char* src = fB + (size_t)(s + 1) * B_BYTES + tid * 128;
#pragma unroll
                for (int q = 0; q < 8; ++q) CP_ASYNC16(dst + q * 16, src + q * 16);
            }
            CP_COMMIT();
            const size_t k0 = (size_t)(s + 1) * BK;
#pragma unroll
            for (int i = 0; i < 4; ++i) {
                nv[i] = *(const float4*)(nrow + k0 + i * 4);
                ev[i] = *(const float4*)(erow + k0 + i * 4);
            }
        }

        // (b) compute stage s
        const uint32_t sbA = sb + cur;
        const uint32_t sbB = sb + cur + ST_A2;
#pragma unroll
        for (int ks = 0; ks < 4; ++ks) {
            uint32_t b[4][4];
#pragma unroll
            for (int np = 0; np < 4; ++np)
                LDSM_X4(b[np][0], b[np][1], b[np][2], b[np][3],
                        sbB + ((bbase[np] + ks * 32) ^ bxor[np]));
#pragma unroll
            for (int p = 0; p < 2; ++p) {
                uint32_t a[4];
                LDSM_X4(a[0], a[1], a[2], a[3],
                        sbA + p * A_BYTES + ((abase + ks * 32) ^ axor));
#pragma unroll
                for (int np = 0; np < 4; ++np) {
                    mma_f16(acc[p][np * 2],     a, b[np][0], b[np][1]);
                    mma_f16(acc[p][np * 2 + 1], a, b[np][2], b[np][3]);
                }
            }
        }

        // (c) convert + store stage s+1 A tiles; drain B copy; barrier
        if (s + 1 < STAGES) {
            char* bp = smem + ((s + 1) & 1) * STAGE_BYTES;
            uint4 S0, S1, E0, E1;
            S0 = make_uint4(pack_h2(sgnf(nv[0].x), sgnf(nv[0].y)), pack_h2(sgnf(nv[0].z), sgnf(nv[0].w)),
                            pack_h2(sgnf(nv[1].x), sgnf(nv[1].y)), pack_h2(sgnf(nv[1].z), sgnf(nv[1].w)));
            S1 = make_uint4(pack_h2(sgnf(nv[2].x), sgnf(nv[2].y)), pack_h2(sgnf(nv[2].z), sgnf(nv[2].w)),
                            pack_h2(sgnf(nv[3].x), sgnf(nv[3].y)), pack_h2(sgnf(nv[3].z), sgnf(nv[3].w)));
            E0 = make_uint4(pack_h2(ev[0].x, ev[0].y), pack_h2(ev[0].z, ev[0].w),
                            pack_h2(ev[1].x, ev[1].y), pack_h2(ev[1].z, ev[1].w));
            E1 = make_uint4(pack_h2(ev[2].x, ev[2].y), pack_h2(ev[2].z, ev[2].w),
                            pack_h2(ev[3].x, ev[3].y), pack_h2(ev[3].z, ev[3].w));
            *(uint4*)(bp + 0 * A_BYTES + csts0) = S0;
            *(uint4*)(bp + 0 * A_BYTES + csts1) = S1;
            *(uint4*)(bp + 1 * A_BYTES + csts0) = E0;
            *(uint4*)(bp + 1 * A_BYTES + csts1) = E1;
            CP_WAIT0();
            __syncthreads();
        }
    }

    // ---- epilogue: acc -> g_S (fp32) ----
    const int er0 = wm + (lane >> 2);
    const int ec0 = wn + (lane & 3) * 2;
#pragma unroll
    for (int p = 0; p < 2; ++p) {
        float* base = g_S + ((size_t)p * N_NODES + M0 + er0) * F + ec0;
#pragma unroll
        for (int nt = 0; nt < 8; ++nt) {
            *(float2*)(base + nt * 8)         = make_float2(acc[p][nt][0], acc[p][nt][1]);
            *(float2*)(base + 8 * F + nt * 8) = make_float2(acc[p][nt][2], acc[p][nt][3]);
        }
    }
}

// ---------------------------------------------------------------------------
// Combine: out = relu(S_sign@Wd + b2) + S_edge@We + eb
// ---------------------------------------------------------------------------
__device__ __forceinline__ void accum_block(const float* __restrict__ W,
                                            const float* __restrict__ S,
                                            float* acc,
                                            float* Ws, float* Ss,
                                            int tid, int tx, int ty, int R0) {
#pragma unroll 1
    for (int k0 = 0; k0 < 128; k0 += 32) {
        __syncthreads();
#pragma unroll
        for (int i = 0; i < 4; ++i) {
            const int e = tid + i * 256;
            const int wrow = e >> 5;
            const int wc = (e & 31) * 4;
            *(float4*)(Ws + wrow * 128 + wc) = *(const float4*)(W + (k0 + wrow) * 128 + wc);
        }
        {
            const int srow = tid >> 3;
            const int sc = (tid & 7) * 4;
            *(float4*)(Ss + srow * 36 + sc) =
                *(const float4*)(S + (size_t)(R0 + srow) * F + k0 + sc);
        }
        __syncthreads();
#pragma unroll 8
        for (int kk = 0; kk < 32; ++kk) {
            float w[4], sv[4];
#pragma unroll
            for (int v = 0; v < 4; ++v) w[v] = Ws[kk * 128 + tx + 32 * v];
#pragma unroll
            for (int u = 0; u < 4; ++u) sv[u] = Ss[(ty + 8 * u) * 36 + kk];
#pragma unroll
            for (int u = 0; u < 4; ++u)
#pragma unroll
                for (int v = 0; v < 4; ++v)
                    acc[u * 4 + v] = fmaf(sv[u], w[v], acc[u * 4 + v]);
        }
    }
}

__global__ __launch_bounds__(256)
void combine_kernel(const float* __restrict__ edge_weight,
                    const float* __restrict__ edge_bias,
                    float* __restrict__ out) {
    __shared__ float Ws[32 * 128];
    __shared__ float Ss[32 * 36];

    const int tid = threadIdx.x;
    const int tx = tid & 31;
    const int ty = tid >> 5;
    const int R0 = blockIdx.x * 32;

    float accN[16], accE[16];
#pragma unroll
    for (int i = 0; i < 16; ++i) { accN[i] = 0.f; accE[i] = 0.f; }

    accum_block(g_Wd,        g_S,                        accN, Ws, Ss, tid, tx, ty, R0);
    accum_block(edge_weight, g_S + (size_t)N_NODES * F,  accE, Ws, Ss, tid, tx, ty, R0);

    float b2[4], eb[4];
#pragma unroll
    for (int v = 0; v < 4; ++v) {
        b2[v] = g_b2[tx + 32 * v];
        eb[v] = edge_bias[tx + 32 * v];
    }
#pragma unroll
    for (int u = 0; u < 4; ++u)
#pragma unroll
        for (int v = 0; v < 4; ++v) {
            const int r = R0 + ty + 8 * u;
            const int c = tx + 32 * v;
            out[(size_t)r * F + c] =
                fmaxf(accN[u * 4 + v] + b2[v], 0.f) + accE[u * 4 + v] + eb[v];
        }
}

extern "C" void kernel_launch(void* const* d_in, const int* in_sizes, int n_in,
                              void* d_out, int out_size) {
    const float* feats       = (const float*)d_in[0];
    const float* node_adj    = (const float*)d_in[1];
    const float* edge_adj    = (const float*)d_in[2];
    const float* node_weight = (const float*)d_in[3];
    const float* node_bias   = (const float*)d_in[4];
    const float* edge_weight = (const float*)d_in[5];
    const float* edge_bias   = (const float*)d_in[6];
    float* out = (float*)d_out;

    cudaFuncSetAttribute(spmm2_f16, cudaFuncAttributeMaxDynamicSharedMemorySize, SMEM_TOTAL);

    zero_c_kernel<<<1, 128>>>();
    colsum_kernel<<<96, 128>>>(feats);
    wtrans_kernel<<<1, 128>>>(node_weight, node_bias);
    prep_feats<<<STAGES, 256>>>(feats);
    spmm2_f16<<<GRID, THREADS, SMEM_TOTAL>>>(node_adj, edge_adj);
    combine_kernel<<<N_NODES / 32, 256>>>(edge_weight, edge_bias, out);
}